// round 3
// baseline (speedup 1.0000x reference)
#include <cuda_runtime.h>
#include <cuda_bf16.h>
#include <cstdint>

#define HH 256
#define WW 256
#define CC 64
#define BB 2
#define NNODES (BB * HH * WW)
#define NEG_SLOPE 0.2f
#define STEP (2.0f / 255.0f)

// scratch: attention logits per node
__device__ float g_asrc[NNODES];
__device__ float g_adst[NNODES];

// ---------------------------------------------------------------------------
// K1: per-node a_src = xg . (W @ att_src), a_dst = xg . (W @ att_dst)
// Block = one (b,y) row, 256 threads = 256 x positions.
// ---------------------------------------------------------------------------
__global__ __launch_bounds__(256) void gat_k1(
    const float* __restrict__ x,
    const float* __restrict__ pos_w,
    const float* __restrict__ pos_b,
    const float* __restrict__ lin_w,
    const float* __restrict__ att_src,
    const float* __restrict__ att_dst)
{
    __shared__ float ws[64], wd[64];
    __shared__ float as_s[64], ad_s[64];
    __shared__ float pw0[64], pw1[64], pb_s[64];

    const int tid = threadIdx.x;
    const int row = blockIdx.x;          // 0..511
    const int b = row >> 8;
    const int y = row & 255;

    if (tid < 64) {
        as_s[tid] = att_src[tid];
        ad_s[tid] = att_dst[tid];
        pw0[tid]  = pos_w[tid];
        pw1[tid]  = pos_w[64 + tid];
        pb_s[tid] = pos_b[tid];
    }
    __syncthreads();

    if (tid < 64) {
        float s = 0.0f, d = 0.0f;
        const float* lw = lin_w + tid * 64;
        #pragma unroll 8
        for (int co = 0; co < 64; co++) {
            float w = lw[co];
            s = fmaf(w, as_s[co], s);
            d = fmaf(w, ad_s[co], d);
        }
        ws[tid] = s;
        wd[tid] = d;
    }
    __syncthreads();

    const float py = -1.0f + (float)y * STEP;
    const float px = -1.0f + (float)tid * STEP;

    float s = 0.0f, d = 0.0f;
    const float* xp = x + (((size_t)b << 22) | ((size_t)y << 8)) + tid;
    #pragma unroll 8
    for (int c = 0; c < 64; c++) {
        float v = xp[(size_t)c << 16];
        v += fmaf(px, pw1[c], fmaf(py, pw0[c], pb_s[c]));
        s = fmaf(v, ws[c], s);
        d = fmaf(v, wd[c], d);
    }
    const int node = (b << 16) + (y << 8) + tid;
    g_asrc[node] = s;
    g_adst[node] = d;
}

// ---------------------------------------------------------------------------
// K2: one thread per node.
//   alpha (9) from a_src halo + a_dst; z[64] = sum_j alpha_j * xg[src_j]
//   (aggregated in registers over 4 channel chunks of 16, staged in SMEM);
//   out = z @ W + bias (W broadcast from SMEM).
// Block = 128 nodes (half a row), 128 threads. Grid = 1024.
// ---------------------------------------------------------------------------
#define XT 128
#define XH 130
#define CK 16
#define HST 132   // hs row stride (floats)

__global__ __launch_bounds__(128, 4) void gat_k2(
    const float* __restrict__ x,
    const float* __restrict__ lin_w,
    const float* __restrict__ pos_w,
    const float* __restrict__ pos_b,
    const float* __restrict__ bias,
    float* __restrict__ out)
{
    __shared__ float hs[3 * CK * HST];   // [ (cl*3+ry) ][ xi ] ; reused for W
    __shared__ float as_sh[3 * HST];
    __shared__ float pw0[64], pw1[64], pb_s[64], b_s[64];

    const int tid = threadIdx.x;
    const int blk = blockIdx.x;          // 0..1023
    const int b  = blk >> 9;
    const int r  = blk & 511;
    const int y  = r >> 1;
    const int x0 = (r & 1) << 7;

    if (tid < 64) {
        pw0[tid]  = pos_w[tid];
        pw1[tid]  = pos_w[64 + tid];
        pb_s[tid] = pos_b[tid];
        b_s[tid]  = bias[tid];
    }

    // stage a_src halo: 3 rows x 130, OOB = -1e30 (=> alpha 0)
    for (int i = tid; i < 3 * XH; i += 128) {
        int ry = i / XH;
        int xi = i - ry * XH;
        int yy = y - 1 + ry;
        int xg = x0 - 1 + xi;
        float v = -1e30f;
        if ((unsigned)yy < 256u && (unsigned)xg < 256u)
            v = g_asrc[(b << 16) + (yy << 8) + xg];
        as_sh[ry * HST + xi] = v;
    }
    __syncthreads();

    // ---- attention weights (per thread/node) ----
    const int xl = tid;
    const int xd = x0 + xl;
    const float ad = g_adst[(b << 16) + (y << 8) + xd];

    float alpha[9];
    float m = -1e30f;
    #pragma unroll
    for (int j = 0; j < 9; j++) {
        const int ry = j / 3, cx = j % 3;
        float e = as_sh[ry * HST + xl + cx] + ad;
        e = (e >= 0.0f) ? e : NEG_SLOPE * e;
        alpha[j] = e;
        m = fmaxf(m, e);
    }
    float ssum = 0.0f;
    #pragma unroll
    for (int j = 0; j < 9; j++) {
        float p = expf(alpha[j] - m);
        alpha[j] = p;
        ssum += p;
    }
    const float inv = 1.0f / ssum;
    #pragma unroll
    for (int j = 0; j < 9; j++) alpha[j] *= inv;

    // per-halo-row y positional coordinate (BUGFIX vs R2: pe must use the
    // neighbor row's y, not the dst row's y)
    float pyr[3];
    #pragma unroll
    for (int ry = 0; ry < 3; ry++)
        pyr[ry] = -1.0f + (float)(y - 1 + ry) * STEP;

    // ---- aggregate z[64] in registers, 4 channel chunks ----
    float z[64];
    const float* xbase = x + (((size_t)b << 22)) + ((size_t)y << 8) + x0 - 1;

    #pragma unroll
    for (int p = 0; p < 4; p++) {
        const int c0 = p * CK;
        __syncthreads();   // protect hs reuse across passes

        // stage xg halo chunk: 16 channels x 3 rows x 130 x
        #pragma unroll 4
        for (int cl = 0; cl < CK; cl++) {
            const int c = c0 + cl;
            const float w0c = pw0[c];
            const float pbc = pb_s[c];
            const float w1  = pw1[c];
            const float* xc = xbase + ((size_t)c << 16);
            #pragma unroll
            for (int ry = 0; ry < 3; ry++) {
                const int yy = y - 1 + ry;
                const bool rowok = (unsigned)yy < 256u;
                const float pey = fmaf(pyr[ry], w0c, pbc);
                const float* src = xc + ((ry - 1) << 8);
                float* dst = &hs[(cl * 3 + ry) * HST];
                {
                    const int xg = x0 - 1 + tid;
                    float v = 0.0f;
                    if (rowok && (unsigned)xg < 256u) {
                        const float px = -1.0f + (float)xg * STEP;
                        v = src[tid] + fmaf(px, w1, pey);
                    }
                    dst[tid] = v;
                }
                if (tid < 2) {
                    const int xi = 128 + tid;
                    const int xg = x0 - 1 + xi;
                    float v = 0.0f;
                    if (rowok && (unsigned)xg < 256u) {
                        const float px = -1.0f + (float)xg * STEP;
                        v = src[xi] + fmaf(px, w1, pey);
                    }
                    dst[xi] = v;
                }
            }
        }
        __syncthreads();

        // aggregate this chunk
        #pragma unroll
        for (int cl = 0; cl < CK; cl++) {
            const float* hb = &hs[cl * 3 * HST + xl];
            float acc = 0.0f;
            #pragma unroll
            for (int ry = 0; ry < 3; ry++) {
                #pragma unroll
                for (int cx = 0; cx < 3; cx++)
                    acc = fmaf(alpha[ry * 3 + cx], hb[ry * HST + cx], acc);
            }
            z[c0 + cl] = acc;
        }
    }

    // ---- stage W [k][co] into hs (broadcast operand) ----
    __syncthreads();
    {
        float4* wp = (float4*)hs;
        const float4* lw4 = (const float4*)lin_w;
        #pragma unroll
        for (int i = 0; i < 8; i++)
            wp[tid + i * 128] = lw4[tid + i * 128];
    }
    __syncthreads();

    // ---- per-thread GEMM: out[co] = z . W[:,co] + bias, 4 chunks of 16 ----
    float* outp = out + (((size_t)b << 22)) + ((size_t)y << 8) + xd;
    #pragma unroll
    for (int cc = 0; cc < 4; cc++) {
        const int c0 = cc * 16;
        float acc0 = b_s[c0 + 0],  acc1 = b_s[c0 + 1],  acc2 = b_s[c0 + 2],  acc3 = b_s[c0 + 3];
        float acc4 = b_s[c0 + 4],  acc5 = b_s[c0 + 5],  acc6 = b_s[c0 + 6],  acc7 = b_s[c0 + 7];
        float acc8 = b_s[c0 + 8],  acc9 = b_s[c0 + 9],  accA = b_s[c0 + 10], accB = b_s[c0 + 11];
        float accC = b_s[c0 + 12], accD = b_s[c0 + 13], accE = b_s[c0 + 14], accF = b_s[c0 + 15];
        #pragma unroll
        for (int k = 0; k < 64; k++) {
            const float zk = z[k];
            const float4 w0 = *(const float4*)&hs[k * 64 + c0];
            const float4 w1 = *(const float4*)&hs[k * 64 + c0 + 4];
            const float4 w2 = *(const float4*)&hs[k * 64 + c0 + 8];
            const float4 w3 = *(const float4*)&hs[k * 64 + c0 + 12];
            acc0 = fmaf(zk, w0.x, acc0); acc1 = fmaf(zk, w0.y, acc1);
            acc2 = fmaf(zk, w0.z, acc2); acc3 = fmaf(zk, w0.w, acc3);
            acc4 = fmaf(zk, w1.x, acc4); acc5 = fmaf(zk, w1.y, acc5);
            acc6 = fmaf(zk, w1.z, acc6); acc7 = fmaf(zk, w1.w, acc7);
            acc8 = fmaf(zk, w2.x, acc8); acc9 = fmaf(zk, w2.y, acc9);
            accA = fmaf(zk, w2.z, accA); accB = fmaf(zk, w2.w, accB);
            accC = fmaf(zk, w3.x, accC); accD = fmaf(zk, w3.y, accD);
            accE = fmaf(zk, w3.z, accE); accF = fmaf(zk, w3.w, accF);
        }
        outp[((size_t)(c0 + 0))  << 16] = acc0;
        outp[((size_t)(c0 + 1))  << 16] = acc1;
        outp[((size_t)(c0 + 2))  << 16] = acc2;
        outp[((size_t)(c0 + 3))  << 16] = acc3;
        outp[((size_t)(c0 + 4))  << 16] = acc4;
        outp[((size_t)(c0 + 5))  << 16] = acc5;
        outp[((size_t)(c0 + 6))  << 16] = acc6;
        outp[((size_t)(c0 + 7))  << 16] = acc7;
        outp[((size_t)(c0 + 8))  << 16] = acc8;
        outp[((size_t)(c0 + 9))  << 16] = acc9;
        outp[((size_t)(c0 + 10)) << 16] = accA;
        outp[((size_t)(c0 + 11)) << 16] = accB;
        outp[((size_t)(c0 + 12)) << 16] = accC;
        outp[((size_t)(c0 + 13)) << 16] = accD;
        outp[((size_t)(c0 + 14)) << 16] = accE;
        outp[((size_t)(c0 + 15)) << 16] = accF;
    }
}

// ---------------------------------------------------------------------------
extern "C" void kernel_launch(void* const* d_in, const int* in_sizes, int n_in,
                              void* d_out, int out_size)
{
    const float* x       = (const float*)d_in[0];
    const float* pos_w   = (const float*)d_in[1];
    const float* pos_b   = (const float*)d_in[2];
    const float* lin_w   = (const float*)d_in[3];
    const float* att_src = (const float*)d_in[4];
    const float* att_dst = (const float*)d_in[5];
    const float* bias    = (const float*)d_in[6];
    // d_in[7], d_in[8]: edge lists — fixed 3x3 stencil, not needed.
    float* out = (float*)d_out;

    gat_k1<<<512, 256>>>(x, pos_w, pos_b, lin_w, att_src, att_dst);
    gat_k2<<<1024, 128>>>(x, lin_w, pos_w, pos_b, bias, out);
}

// round 4
// speedup vs baseline: 1.9146x; 1.9146x over previous
#include <cuda_runtime.h>
#include <cuda_bf16.h>
#include <cstdint>

#define NNODES (2 * 256 * 256)
#define NEG_SLOPE 0.2f
#define STEP (2.0f / 255.0f)
#define HST 68   // xh inner stride

__device__ float g_asrc[NNODES];
__device__ float g_adst[NNODES];

// ---------------------------------------------------------------------------
// K1: per-node a_src = xg.(W@att_src), a_dst = xg.(W@att_dst)
// ---------------------------------------------------------------------------
__global__ __launch_bounds__(256) void gat_k1(
    const float* __restrict__ x,
    const float* __restrict__ pos_w,
    const float* __restrict__ pos_b,
    const float* __restrict__ lin_w,
    const float* __restrict__ att_src,
    const float* __restrict__ att_dst)
{
    __shared__ float ws[64], wd[64];
    __shared__ float as_s[64], ad_s[64];
    __shared__ float pw0[64], pw1[64], pb_s[64];

    const int tid = threadIdx.x;
    const int row = blockIdx.x;
    const int b = row >> 8;
    const int y = row & 255;

    if (tid < 64) {
        as_s[tid] = att_src[tid];
        ad_s[tid] = att_dst[tid];
        pw0[tid]  = pos_w[tid];
        pw1[tid]  = pos_w[64 + tid];
        pb_s[tid] = pos_b[tid];
    }
    __syncthreads();

    if (tid < 64) {
        float s = 0.0f, d = 0.0f;
        const float* lw = lin_w + tid * 64;
        #pragma unroll 8
        for (int co = 0; co < 64; co++) {
            float w = lw[co];
            s = fmaf(w, as_s[co], s);
            d = fmaf(w, ad_s[co], d);
        }
        ws[tid] = s;
        wd[tid] = d;
    }
    __syncthreads();

    const float py = -1.0f + (float)y * STEP;
    const float px = -1.0f + (float)tid * STEP;

    float s = 0.0f, d = 0.0f;
    const float* xp = x + (((size_t)b << 22) | ((size_t)y << 8)) + tid;
    #pragma unroll 8
    for (int c = 0; c < 64; c++) {
        float v = xp[(size_t)c << 16];
        v += fmaf(px, pw1[c], fmaf(py, pw0[c], pb_s[c]));
        s = fmaf(v, ws[c], s);
        d = fmaf(v, wd[c], d);
    }
    const int node = (b << 16) + (y << 8) + tid;
    g_asrc[node] = s;
    g_adst[node] = d;
}

// ---------------------------------------------------------------------------
// K2: block = 64 x-positions of one (b,y) row, 256 threads.
//  Phase A: alpha[9] per node (in regs, computed by all 4 threads sharing x)
//  Phase B: 4 channel-chunks: stage xg halo -> aggregate into zs[k][x] (SMEM)
//  Phase C: block GEMM out[x][co] = zs[:, x] . W[:, co] + bias
// ---------------------------------------------------------------------------
__global__ __launch_bounds__(256, 4) void gat_k2(
    const float* __restrict__ x,
    const float* __restrict__ lin_w,
    const float* __restrict__ pos_w,
    const float* __restrict__ pos_b,
    const float* __restrict__ bias,
    float* __restrict__ out)
{
    __shared__ float xh[16 * 3 * HST];   // [cl][ry][xi]
    __shared__ float zs[64 * 64];        // [k][x]
    __shared__ float wsm[64 * 64];       // [k][co]
    __shared__ float as_sh[3 * HST];
    __shared__ float pw0[64], pw1[64], pb_s[64], b_s[64];

    const int tid = threadIdx.x;
    const int blk = blockIdx.x;          // 2048 blocks
    const int b  = blk >> 10;
    const int r  = blk & 1023;
    const int y  = r >> 2;
    const int x0 = (r & 3) << 6;

    if (tid < 64) {
        pw0[tid]  = pos_w[tid];
        pw1[tid]  = pos_w[64 + tid];
        pb_s[tid] = pos_b[tid];
        b_s[tid]  = bias[tid];
    }

    // stage W [k][co] (float4)
    {
        float4* wp = (float4*)wsm;
        const float4* lw4 = (const float4*)lin_w;
        #pragma unroll
        for (int i = 0; i < 4; i++)
            wp[tid + i * 256] = lw4[tid + i * 256];
    }

    // stage a_src halo: 3 rows x 66, OOB = -1e30
    if (tid < 198) {
        int ry = tid / 66;
        int xi = tid - ry * 66;
        int yy = y - 1 + ry;
        int xg = x0 - 1 + xi;
        float v = -1e30f;
        if ((unsigned)yy < 256u && (unsigned)xg < 256u)
            v = g_asrc[(b << 16) + (yy << 8) + xg];
        as_sh[ry * HST + xi] = v;
    }
    __syncthreads();

    // ---- alpha (registers; 4 threads per x compute redundantly) ----
    const int xl = tid & 63;
    const float ad = g_adst[(b << 16) + (y << 8) + x0 + xl];
    float alpha[9];
    float m = -1e30f;
    #pragma unroll
    for (int ry = 0; ry < 3; ry++) {
        #pragma unroll
        for (int cx = 0; cx < 3; cx++) {
            float e = as_sh[ry * HST + xl + cx] + ad;
            e = (e >= 0.0f) ? e : NEG_SLOPE * e;
            alpha[ry * 3 + cx] = e;
            m = fmaxf(m, e);
        }
    }
    float ssum = 0.0f;
    #pragma unroll
    for (int j = 0; j < 9; j++) {
        float p = expf(alpha[j] - m);
        alpha[j] = p;
        ssum += p;
    }
    const float inv = 1.0f / ssum;
    #pragma unroll
    for (int j = 0; j < 9; j++) alpha[j] *= inv;

    // ---- aggregation into zs, 4 channel chunks of 16 ----
    const int wid  = tid >> 5;
    const int lane = tid & 31;
    const int cq   = tid >> 6;   // 0..3: this thread's channel sub-group

    #pragma unroll 1
    for (int p = 0; p < 4; p++) {
        const int c0 = p * 16;
        __syncthreads();  // xh reuse

        // stage xh: 48 (cl,ry) pairs, 6 per warp, 66 xi each
        #pragma unroll 1
        for (int i = 0; i < 6; i++) {
            const int pp = wid * 6 + i;
            const int cl = pp / 3;
            const int ry = pp - cl * 3;
            const int c  = c0 + cl;
            const int yy = y - 1 + ry;
            const bool rowok = (unsigned)yy < 256u;
            const float pey = fmaf(-1.0f + (float)yy * STEP, pw0[c], pb_s[c]);
            const float w1  = pw1[c];
            const float* src = x + (((size_t)(b * 64 + c)) << 16) + (yy << 8);
            float* dst = &xh[(cl * 3 + ry) * HST];
            #pragma unroll
            for (int pass = 0; pass < 3; pass++) {
                const int xi = pass * 32 + lane;
                if (xi < 66) {
                    const int xg = x0 - 1 + xi;
                    float v = 0.0f;
                    if (rowok && (unsigned)xg < 256u)
                        v = src[xg] + fmaf(-1.0f + (float)xg * STEP, w1, pey);
                    dst[xi] = v;
                }
            }
        }
        __syncthreads();

        // aggregate: thread handles channels c0 + cq*4 .. +3 for its x
        #pragma unroll
        for (int q = 0; q < 4; q++) {
            const int cl = cq * 4 + q;
            const float* hb = &xh[cl * 3 * HST + xl];
            float acc = 0.0f;
            #pragma unroll
            for (int ry = 0; ry < 3; ry++) {
                #pragma unroll
                for (int cx = 0; cx < 3; cx++)
                    acc = fmaf(alpha[ry * 3 + cx], hb[ry * HST + cx], acc);
            }
            zs[(c0 + cl) * 64 + xl] = acc;
        }
    }
    __syncthreads();

    // ---- block GEMM: out[x][co] = zs[:,x] . W[:,co] + bias ----
    const int xq   = tid & 15;    // x-quad
    const int cq16 = tid >> 4;    // co-quad
    const float4* zs4 = (const float4*)zs;
    const float4* w4  = (const float4*)wsm;

    float4 a0, a1, a2, a3;
    {
        const int co0 = cq16 * 4;
        a0 = make_float4(b_s[co0],     b_s[co0],     b_s[co0],     b_s[co0]);
        a1 = make_float4(b_s[co0 + 1], b_s[co0 + 1], b_s[co0 + 1], b_s[co0 + 1]);
        a2 = make_float4(b_s[co0 + 2], b_s[co0 + 2], b_s[co0 + 2], b_s[co0 + 2]);
        a3 = make_float4(b_s[co0 + 3], b_s[co0 + 3], b_s[co0 + 3], b_s[co0 + 3]);
    }

    #pragma unroll 8
    for (int k = 0; k < 64; k++) {
        const float4 zv = zs4[k * 16 + xq];
        const float4 wv = w4[k * 16 + cq16];
        a0.x = fmaf(zv.x, wv.x, a0.x); a0.y = fmaf(zv.y, wv.x, a0.y);
        a0.z = fmaf(zv.z, wv.x, a0.z); a0.w = fmaf(zv.w, wv.x, a0.w);
        a1.x = fmaf(zv.x, wv.y, a1.x); a1.y = fmaf(zv.y, wv.y, a1.y);
        a1.z = fmaf(zv.z, wv.y, a1.z); a1.w = fmaf(zv.w, wv.y, a1.w);
        a2.x = fmaf(zv.x, wv.z, a2.x); a2.y = fmaf(zv.y, wv.z, a2.y);
        a2.z = fmaf(zv.z, wv.z, a2.z); a2.w = fmaf(zv.w, wv.z, a2.w);
        a3.x = fmaf(zv.x, wv.w, a3.x); a3.y = fmaf(zv.y, wv.w, a3.y);
        a3.z = fmaf(zv.z, wv.w, a3.z); a3.w = fmaf(zv.w, wv.w, a3.w);
    }

    {
        const int co0 = cq16 * 4;
        float* ob = out + (((size_t)b) << 22) + (y << 8) + x0 + xq * 4;
        *(float4*)(ob + ((size_t)(co0 + 0) << 16)) = a0;
        *(float4*)(ob + ((size_t)(co0 + 1) << 16)) = a1;
        *(float4*)(ob + ((size_t)(co0 + 2) << 16)) = a2;
        *(float4*)(ob + ((size_t)(co0 + 3) << 16)) = a3;
    }
}

// ---------------------------------------------------------------------------
extern "C" void kernel_launch(void* const* d_in, const int* in_sizes, int n_in,
                              void* d_out, int out_size)
{
    const float* x       = (const float*)d_in[0];
    const float* pos_w   = (const float*)d_in[1];
    const float* pos_b   = (const float*)d_in[2];
    const float* lin_w   = (const float*)d_in[3];
    const float* att_src = (const float*)d_in[4];
    const float* att_dst = (const float*)d_in[5];
    const float* bias    = (const float*)d_in[6];
    float* out = (float*)d_out;

    gat_k1<<<512, 256>>>(x, pos_w, pos_b, lin_w, att_src, att_dst);
    gat_k2<<<2048, 256>>>(x, lin_w, pos_w, pos_b, bias, out);
}

// round 5
// speedup vs baseline: 2.5022x; 1.3069x over previous
#include <cuda_runtime.h>
#include <cuda_bf16.h>
#include <cstdint>

#define NEG_SLOPE 0.2f
#define STEP (2.0f / 255.0f)
#define AST 132

__device__ float g_asrc[131072];
__device__ float g_adst[131072];

// ---------------------------------------------------------------------------
// K1: per-node a_src = xg.(W@att_src), a_dst = xg.(W@att_dst)
// ---------------------------------------------------------------------------
__global__ __launch_bounds__(256) void gat_k1(
    const float* __restrict__ x,
    const float* __restrict__ pos_w,
    const float* __restrict__ pos_b,
    const float* __restrict__ lin_w,
    const float* __restrict__ att_src,
    const float* __restrict__ att_dst)
{
    __shared__ float ws[64], wd[64];
    __shared__ float as_s[64], ad_s[64];
    __shared__ float pw0[64], pw1[64], pb_s[64];

    const int tid = threadIdx.x;
    const int row = blockIdx.x;
    const int b = row >> 8;
    const int y = row & 255;

    if (tid < 64) {
        as_s[tid] = att_src[tid];
        ad_s[tid] = att_dst[tid];
        pw0[tid]  = pos_w[tid];
        pw1[tid]  = pos_w[64 + tid];
        pb_s[tid] = pos_b[tid];
    }
    __syncthreads();

    if (tid < 64) {
        float s = 0.0f, d = 0.0f;
        const float* lw = lin_w + tid * 64;
        #pragma unroll 8
        for (int co = 0; co < 64; co++) {
            float w = lw[co];
            s = fmaf(w, as_s[co], s);
            d = fmaf(w, ad_s[co], d);
        }
        ws[tid] = s;
        wd[tid] = d;
    }
    __syncthreads();

    const float py = -1.0f + (float)y * STEP;
    const float px = -1.0f + (float)tid * STEP;

    float s = 0.0f, d = 0.0f;
    const float* xp = x + (((size_t)b << 22) | ((size_t)y << 8)) + tid;
    #pragma unroll 8
    for (int c = 0; c < 64; c++) {
        float v = xp[(size_t)c << 16];
        v += fmaf(px, pw1[c], fmaf(py, pw0[c], pb_s[c]));
        s = fmaf(v, ws[c], s);
        d = fmaf(v, wd[c], d);
    }
    const int node = (b << 16) + (y << 8) + tid;
    g_asrc[node] = s;
    g_adst[node] = d;
}

// ---------------------------------------------------------------------------
// K2: block = one (b, y) row, 128 x positions, 256 threads.
//   Warp (seg = wid&3, half = wid>>2): x in [x0+seg*32, +32), channels
//   half*32..+31. Shuffle-based 3x3 aggregation straight into zs[k][x]
//   (no staging SMEM, no barriers). Then one block GEMM out = zs.W + bias.
// ---------------------------------------------------------------------------
__global__ __launch_bounds__(256, 4) void gat_k2(
    const float* __restrict__ x,
    const float* __restrict__ lin_w,
    const float* __restrict__ pos_w,
    const float* __restrict__ pos_b,
    const float* __restrict__ bias,
    float* __restrict__ out)
{
    __shared__ float zs[64 * 128];   // [k][x]  32 KB
    __shared__ float wsm[64 * 64];   // [k][co] 16 KB
    __shared__ float as_sh[3 * AST];
    __shared__ float pw0[64], pw1[64], pb_s[64], b_s[64];

    const int tid  = threadIdx.x;
    const int lane = tid & 31;
    const int wid  = tid >> 5;
    const int blk  = blockIdx.x;       // 1024
    const int b  = blk >> 9;
    const int r  = blk & 511;
    const int y  = r >> 1;
    const int x0 = (r & 1) << 7;

    if (tid < 64) {
        pw0[tid]  = pos_w[tid];
        pw1[tid]  = pos_w[64 + tid];
        pb_s[tid] = pos_b[tid];
        b_s[tid]  = bias[tid];
    }

    // stage W [k][co]
    {
        float4* wp = (float4*)wsm;
        const float4* lw4 = (const float4*)lin_w;
        #pragma unroll
        for (int i = 0; i < 4; i++)
            wp[tid + i * 256] = lw4[tid + i * 256];
    }

    // stage a_src halo: 3 rows x 130
    for (int i = tid; i < 3 * 130; i += 256) {
        int ry = i / 130;
        int xi = i - ry * 130;
        int yy = y - 1 + ry;
        int xg = x0 - 1 + xi;
        float v = -1e30f;
        if ((unsigned)yy < 256u && (unsigned)xg < 256u)
            v = g_asrc[(b << 16) + (yy << 8) + xg];
        as_sh[ry * AST + xi] = v;
    }
    __syncthreads();

    const int seg  = wid & 3;
    const int half = wid >> 2;
    const int xl   = seg * 32 + lane;   // local x
    const int xd   = x0 + xl;           // global x

    // ---- alpha (registers) ----
    const float ad = g_adst[(b << 16) + (y << 8) + xd];
    float alpha[9];
    float m = -1e30f;
    #pragma unroll
    for (int ry = 0; ry < 3; ry++) {
        #pragma unroll
        for (int cx = 0; cx < 3; cx++) {
            float e = as_sh[ry * AST + xl + cx] + ad;
            e = (e >= 0.0f) ? e : NEG_SLOPE * e;
            alpha[ry * 3 + cx] = e;
            m = fmaxf(m, e);
        }
    }
    float ssum = 0.0f;
    #pragma unroll
    for (int j = 0; j < 9; j++) {
        float p = expf(alpha[j] - m);
        alpha[j] = p;
        ssum += p;
    }
    const float inv = 1.0f / ssum;
    #pragma unroll
    for (int j = 0; j < 9; j++) alpha[j] *= inv;

    // ---- shuffle-based aggregation into zs ----
    const int xs_g = x0 + seg * 32;           // global x of lane 0
    const float pxa = -1.0f + (float)(xs_g - 1 + lane) * STEP;
    const float pxb = -1.0f + (float)(xs_g + 31 + lane) * STEP;
    const bool aok = (xs_g - 1 + lane) >= 0;
    const bool bok = (lane < 2) && (xs_g + 31 + lane) < 256;

    // clamped row indices (invalid rows neutralized by alpha == 0)
    int yyc[3];
    float pey_y[3];
    #pragma unroll
    for (int ry = 0; ry < 3; ry++) {
        int yy = y - 1 + ry;
        int yc = yy < 0 ? 0 : (yy > 255 ? 255 : yy);
        yyc[ry] = yc;
        pey_y[ry] = -1.0f + (float)yy * STEP;
    }

    const float* xb = x + ((size_t)b << 22) + ((size_t)(half * 32) << 16);

    #pragma unroll 2
    for (int ci = 0; ci < 32; ci++) {
        const int c = half * 32 + ci;
        const float w0c = pw0[c];
        const float w1c = pw1[c];
        const float pbc = pb_s[c];
        const float* xc = xb + ((size_t)ci << 16);

        // issue all row loads up front (branchless, MLP)
        float a0 = 0.f, a1 = 0.f, a2 = 0.f;
        float bb0 = 0.f, bb1 = 0.f, bb2 = 0.f;
        const float* r0 = xc + (yyc[0] << 8);
        const float* r1 = xc + (yyc[1] << 8);
        const float* r2 = xc + (yyc[2] << 8);
        if (aok) {
            a0 = r0[xs_g - 1 + lane];
            a1 = r1[xs_g - 1 + lane];
            a2 = r2[xs_g - 1 + lane];
        }
        if (bok) {
            bb0 = r0[xs_g + 31 + lane];
            bb1 = r1[xs_g + 31 + lane];
            bb2 = r2[xs_g + 31 + lane];
        }

        float zacc = 0.0f;
        #pragma unroll
        for (int ry = 0; ry < 3; ry++) {
            float a  = (ry == 0) ? a0  : (ry == 1) ? a1  : a2;
            float bbv = (ry == 0) ? bb0 : (ry == 1) ? bb1 : bb2;
            const float pey = fmaf(pey_y[ry], w0c, pbc);
            // apply positional encoding
            float av = a + fmaf(pxa, w1c, pey);
            float bv = bbv + fmaf(pxb, w1c, pey);
            if (!aok) av = 0.0f;
            if (!bok) bv = 0.0f;

            float b0 = __shfl_sync(0xffffffffu, bv, 0);
            float b1 = __shfl_sync(0xffffffffu, bv, 1);
            float t1 = __shfl_down_sync(0xffffffffu, av, 1);
            float t2 = __shfl_down_sync(0xffffffffu, av, 2);
            if (lane == 31) { t1 = b0; t2 = b1; }
            else if (lane == 30) { t2 = b0; }

            zacc = fmaf(alpha[ry * 3 + 0], av, zacc);
            zacc = fmaf(alpha[ry * 3 + 1], t1, zacc);
            zacc = fmaf(alpha[ry * 3 + 2], t2, zacc);
        }
        zs[c * 128 + xl] = zacc;
    }
    __syncthreads();

    // ---- block GEMM: out[x][co] = zs[:,x] . W[:,co] + bias ----
    const int xq = tid & 31;       // x quad: x = x0 + xq*4 .. +3
    const int cg = tid >> 5;       // co group: co = cg*8 .. +7
    const float4* zs4 = (const float4*)zs;
    const float4* w4  = (const float4*)wsm;

    float4 acc[8];
    #pragma unroll
    for (int j = 0; j < 8; j++) {
        float bv = b_s[cg * 8 + j];
        acc[j] = make_float4(bv, bv, bv, bv);
    }

    #pragma unroll 8
    for (int k = 0; k < 64; k++) {
        const float4 zv = zs4[k * 32 + xq];
        const float4 w0 = w4[k * 16 + cg * 2];
        const float4 w1 = w4[k * 16 + cg * 2 + 1];
        acc[0].x = fmaf(zv.x, w0.x, acc[0].x); acc[0].y = fmaf(zv.y, w0.x, acc[0].y);
        acc[0].z = fmaf(zv.z, w0.x, acc[0].z); acc[0].w = fmaf(zv.w, w0.x, acc[0].w);
        acc[1].x = fmaf(zv.x, w0.y, acc[1].x); acc[1].y = fmaf(zv.y, w0.y, acc[1].y);
        acc[1].z = fmaf(zv.z, w0.y, acc[1].z); acc[1].w = fmaf(zv.w, w0.y, acc[1].w);
        acc[2].x = fmaf(zv.x, w0.z, acc[2].x); acc[2].y = fmaf(zv.y, w0.z, acc[2].y);
        acc[2].z = fmaf(zv.z, w0.z, acc[2].z); acc[2].w = fmaf(zv.w, w0.z, acc[2].w);
        acc[3].x = fmaf(zv.x, w0.w, acc[3].x); acc[3].y = fmaf(zv.y, w0.w, acc[3].y);
        acc[3].z = fmaf(zv.z, w0.w, acc[3].z); acc[3].w = fmaf(zv.w, w0.w, acc[3].w);
        acc[4].x = fmaf(zv.x, w1.x, acc[4].x); acc[4].y = fmaf(zv.y, w1.x, acc[4].y);
        acc[4].z = fmaf(zv.z, w1.x, acc[4].z); acc[4].w = fmaf(zv.w, w1.x, acc[4].w);
        acc[5].x = fmaf(zv.x, w1.y, acc[5].x); acc[5].y = fmaf(zv.y, w1.y, acc[5].y);
        acc[5].z = fmaf(zv.z, w1.y, acc[5].z); acc[5].w = fmaf(zv.w, w1.y, acc[5].w);
        acc[6].x = fmaf(zv.x, w1.z, acc[6].x); acc[6].y = fmaf(zv.y, w1.z, acc[6].y);
        acc[6].z = fmaf(zv.z, w1.z, acc[6].z); acc[6].w = fmaf(zv.w, w1.z, acc[6].w);
        acc[7].x = fmaf(zv.x, w1.w, acc[7].x); acc[7].y = fmaf(zv.y, w1.w, acc[7].y);
        acc[7].z = fmaf(zv.z, w1.w, acc[7].z); acc[7].w = fmaf(zv.w, w1.w, acc[7].w);
    }

    {
        float* ob = out + ((size_t)b << 22) + ((size_t)(cg * 8) << 16)
                        + (y << 8) + x0 + xq * 4;
        #pragma unroll
        for (int j = 0; j < 8; j++)
            *(float4*)(ob + ((size_t)j << 16)) = acc[j];
    }
}

// ---------------------------------------------------------------------------
extern "C" void kernel_launch(void* const* d_in, const int* in_sizes, int n_in,
                              void* d_out, int out_size)
{
    const float* x       = (const float*)d_in[0];
    const float* pos_w   = (const float*)d_in[1];
    const float* pos_b   = (const float*)d_in[2];
    const float* lin_w   = (const float*)d_in[3];
    const float* att_src = (const float*)d_in[4];
    const float* att_dst = (const float*)d_in[5];
    const float* bias    = (const float*)d_in[6];
    float* out = (float*)d_out;

    gat_k1<<<512, 256>>>(x, pos_w, pos_b, lin_w, att_src, att_dst);
    gat_k2<<<1024, 256>>>(x, lin_w, pos_w, pos_b, bias, out);
}

// round 6
// speedup vs baseline: 3.3286x; 1.3303x over previous
#include <cuda_runtime.h>
#include <cuda_bf16.h>
#include <cstdint>

#define NEG_SLOPE 0.2f
#define STEP (2.0f / 255.0f)
#define AST 132

typedef unsigned long long ull;

__device__ float g_asrc[131072];
__device__ float g_adst[131072];

#define FMA2(d, a, b, c) \
    asm("fma.rn.f32x2 %0, %1, %2, %3;" : "=l"(d) : "l"(a), "l"(b), "l"(c))
#define DUP2(d, s) \
    asm("mov.b64 %0, {%1, %1};" : "=l"(d) : "r"(__float_as_uint(s)))
#define PACK2(d, lo, hi) \
    asm("mov.b64 %0, {%1, %2};" : "=l"(d) : "r"(__float_as_uint(lo)), "r"(__float_as_uint(hi)))
#define UNPACK2(lo, hi, s) do { \
    unsigned _ulo, _uhi; \
    asm("mov.b64 {%0, %1}, %2;" : "=r"(_ulo), "=r"(_uhi) : "l"(s)); \
    lo = __uint_as_float(_ulo); hi = __uint_as_float(_uhi); } while (0)

// ---------------------------------------------------------------------------
// K1: per-node a_src = xg.(W@att_src), a_dst = xg.(W@att_dst)
// PE contribution hoisted to 6 scalars; (s,d) accumulated as f32x2.
// ---------------------------------------------------------------------------
__global__ __launch_bounds__(256) void gat_k1(
    const float* __restrict__ x,
    const float* __restrict__ pos_w,
    const float* __restrict__ pos_b,
    const float* __restrict__ lin_w,
    const float* __restrict__ att_src,
    const float* __restrict__ att_dst)
{
    __shared__ float swd[128];          // interleaved (ws, wd) per channel
    __shared__ float as_s[64], ad_s[64];
    __shared__ float pw0[64], pw1[64], pb_s[64];
    __shared__ float sc[6];             // spy_s,spx_s,spb_s,spy_d,spx_d,spb_d

    const int tid = threadIdx.x;
    const int row = blockIdx.x;
    const int b = row >> 8;
    const int y = row & 255;

    if (tid < 64) {
        as_s[tid] = att_src[tid];
        ad_s[tid] = att_dst[tid];
        pw0[tid]  = pos_w[tid];
        pw1[tid]  = pos_w[64 + tid];
        pb_s[tid] = pos_b[tid];
    }
    __syncthreads();

    if (tid < 64) {
        float s = 0.0f, d = 0.0f;
        const float* lw = lin_w + tid * 64;
        #pragma unroll 8
        for (int co = 0; co < 64; co++) {
            float w = lw[co];
            s = fmaf(w, as_s[co], s);
            d = fmaf(w, ad_s[co], d);
        }
        swd[2 * tid]     = s;
        swd[2 * tid + 1] = d;
    }
    __syncthreads();

    if (tid < 6) {
        const int which = tid % 3;          // 0:pw0 1:pw1 2:pb
        const int off   = (tid < 3) ? 0 : 1;
        const float* pv = (which == 0) ? pw0 : (which == 1) ? pw1 : pb_s;
        float acc = 0.0f;
        #pragma unroll 8
        for (int c = 0; c < 64; c++)
            acc = fmaf(pv[c], swd[2 * c + off], acc);
        sc[tid] = acc;
    }
    __syncthreads();

    const float py = -1.0f + (float)y * STEP;
    const float px = -1.0f + (float)tid * STEP;

    ull acc2 = 0ULL;   // (s, d) packed, starts at (0,0)
    const float* xp = x + (((size_t)b << 22) | ((size_t)y << 8)) + tid;
    const ull* wp = (const ull*)swd;
    #pragma unroll 8
    for (int c = 0; c < 64; c++) {
        float v = xp[(size_t)c << 16];
        ull vv; DUP2(vv, v);
        FMA2(acc2, vv, wp[c], acc2);
    }
    float s, d;
    UNPACK2(s, d, acc2);
    s += fmaf(py, sc[0], fmaf(px, sc[1], sc[2]));
    d += fmaf(py, sc[3], fmaf(px, sc[4], sc[5]));

    const int node = (b << 16) + (y << 8) + tid;
    g_asrc[node] = s;
    g_adst[node] = d;
}

// ---------------------------------------------------------------------------
// K2: block = 128 x of one (b,y) row, 256 threads.
//   alpha in regs; PE hoisted to (sumpy, sumpx); aggregation = 9 direct
//   clamped LDGs per channel (OOB neutralized by alpha==0) -> zs[k][x];
//   one barrier; block GEMM with packed fma.rn.f32x2.
// ---------------------------------------------------------------------------
__global__ __launch_bounds__(256, 4) void gat_k2(
    const float* __restrict__ x,
    const float* __restrict__ lin_w,
    const float* __restrict__ pos_w,
    const float* __restrict__ pos_b,
    const float* __restrict__ bias,
    float* __restrict__ out)
{
    __shared__ __align__(16) float zs[64 * 128];   // [k][x]  32 KB
    __shared__ __align__(16) float wsm[64 * 64];   // [k][co] 16 KB
    __shared__ float as_sh[3 * AST];
    __shared__ float pw0[64], pw1[64], pb_s[64], b_s[64];

    const int tid  = threadIdx.x;
    const int lane = tid & 31;
    const int wid  = tid >> 5;
    const int blk  = blockIdx.x;       // 1024
    const int b  = blk >> 9;
    const int r  = blk & 511;
    const int y  = r >> 1;
    const int x0 = (r & 1) << 7;

    if (tid < 64) {
        pw0[tid]  = pos_w[tid];
        pw1[tid]  = pos_w[64 + tid];
        pb_s[tid] = pos_b[tid];
        b_s[tid]  = bias[tid];
    }

    // stage W [k][co]
    {
        float4* wp = (float4*)wsm;
        const float4* lw4 = (const float4*)lin_w;
        #pragma unroll
        for (int i = 0; i < 4; i++)
            wp[tid + i * 256] = lw4[tid + i * 256];
    }

    // stage a_src halo: 3 rows x 130, OOB = -1e30
    for (int i = tid; i < 3 * 130; i += 256) {
        int ry = i / 130;
        int xi = i - ry * 130;
        int yy = y - 1 + ry;
        int xg = x0 - 1 + xi;
        float v = -1e30f;
        if ((unsigned)yy < 256u && (unsigned)xg < 256u)
            v = g_asrc[(b << 16) + (yy << 8) + xg];
        as_sh[ry * AST + xi] = v;
    }
    __syncthreads();

    const int seg  = wid & 3;
    const int half = wid >> 2;
    const int xl   = seg * 32 + lane;
    const int xd   = x0 + xl;

    // ---- alpha ----
    const float ad = g_adst[(b << 16) + (y << 8) + xd];
    float alpha[9];
    float m = -1e30f;
    #pragma unroll
    for (int ry = 0; ry < 3; ry++) {
        #pragma unroll
        for (int cx = 0; cx < 3; cx++) {
            float e = as_sh[ry * AST + xl + cx] + ad;
            e = (e >= 0.0f) ? e : NEG_SLOPE * e;
            alpha[ry * 3 + cx] = e;
            m = fmaxf(m, e);
        }
    }
    float ssum = 0.0f;
    #pragma unroll
    for (int j = 0; j < 9; j++) {
        float p = expf(alpha[j] - m);
        alpha[j] = p;
        ssum += p;
    }
    const float inv = 1.0f / ssum;
    #pragma unroll
    for (int j = 0; j < 9; j++) alpha[j] *= inv;

    // PE hoist: sumpy = sum_j alpha_j * py_j ; sumpx = sum_j alpha_j * px_j
    float sumpy = 0.0f, sumpx = 0.0f;
    #pragma unroll
    for (int ry = 0; ry < 3; ry++) {
        const float pyv = -1.0f + (float)(y - 1 + ry) * STEP;
        #pragma unroll
        for (int cx = 0; cx < 3; cx++) {
            const float pxv = -1.0f + (float)(xd - 1 + cx) * STEP;
            sumpy = fmaf(alpha[ry * 3 + cx], pyv, sumpy);
            sumpx = fmaf(alpha[ry * 3 + cx], pxv, sumpx);
        }
    }

    // clamped row/col offsets (invalid -> alpha==0, contribution exact 0)
    int ro[3];
    #pragma unroll
    for (int ry = 0; ry < 3; ry++) {
        int yy = y - 1 + ry;
        ro[ry] = (yy < 0 ? 0 : (yy > 255 ? 255 : yy)) << 8;
    }
    const int xm  = (xd - 1 < 0)   ? 0   : xd - 1;
    const int xpp = (xd + 1 > 255) ? 255 : xd + 1;

    const float* bb = x + ((size_t)b << 22) + ((size_t)(half << 5) << 16);
    const float* p00 = bb + ro[0] + xm;
    const float* p01 = bb + ro[0] + xd;
    const float* p02 = bb + ro[0] + xpp;
    const float* p10 = bb + ro[1] + xm;
    const float* p11 = bb + ro[1] + xd;
    const float* p12 = bb + ro[1] + xpp;
    const float* p20 = bb + ro[2] + xm;
    const float* p21 = bb + ro[2] + xd;
    const float* p22 = bb + ro[2] + xpp;

    #pragma unroll 8
    for (int ci = 0; ci < 32; ci++) {
        const int c = (half << 5) + ci;
        const size_t co = (size_t)ci << 16;
        const float v00 = p00[co], v01 = p01[co], v02 = p02[co];
        const float v10 = p10[co], v11 = p11[co], v12 = p12[co];
        const float v20 = p20[co], v21 = p21[co], v22 = p22[co];

        float zacc = fmaf(pw0[c], sumpy, fmaf(pw1[c], sumpx, pb_s[c]));
        zacc = fmaf(alpha[0], v00, zacc);
        zacc = fmaf(alpha[1], v01, zacc);
        zacc = fmaf(alpha[2], v02, zacc);
        zacc = fmaf(alpha[3], v10, zacc);
        zacc = fmaf(alpha[4], v11, zacc);
        zacc = fmaf(alpha[5], v12, zacc);
        zacc = fmaf(alpha[6], v20, zacc);
        zacc = fmaf(alpha[7], v21, zacc);
        zacc = fmaf(alpha[8], v22, zacc);
        zs[c * 128 + xl] = zacc;
    }
    __syncthreads();

    // ---- block GEMM (fma.rn.f32x2): thread tile 4 x times 8 co ----
    const int xq = tid & 31;      // x = x0 + xq*4 .. +3
    const int cg = tid >> 5;      // co = cg*8 .. +7
    const float4* zs4 = (const float4*)zs;
    const ull* w8 = (const ull*)wsm;   // [k][co pairs]

    ull acc[4][4];                // [x][co-pair], pair = (co even, co odd)
    {
        ull binit[4];
        #pragma unroll
        for (int p = 0; p < 4; p++)
            PACK2(binit[p], b_s[cg * 8 + 2 * p], b_s[cg * 8 + 2 * p + 1]);
        #pragma unroll
        for (int xi = 0; xi < 4; xi++)
            #pragma unroll
            for (int p = 0; p < 4; p++)
                acc[xi][p] = binit[p];
    }

    #pragma unroll 8
    for (int k = 0; k < 64; k++) {
        const float4 zf = zs4[k * 32 + xq];
        ull z0, z1, z2, z3;
        DUP2(z0, zf.x); DUP2(z1, zf.y); DUP2(z2, zf.z); DUP2(z3, zf.w);
        const ull w0 = w8[k * 32 + cg * 4 + 0];
        const ull w1 = w8[k * 32 + cg * 4 + 1];
        const ull w2 = w8[k * 32 + cg * 4 + 2];
        const ull w3 = w8[k * 32 + cg * 4 + 3];
        FMA2(acc[0][0], z0, w0, acc[0][0]); FMA2(acc[0][1], z0, w1, acc[0][1]);
        FMA2(acc[0][2], z0, w2, acc[0][2]); FMA2(acc[0][3], z0, w3, acc[0][3]);
        FMA2(acc[1][0], z1, w0, acc[1][0]); FMA2(acc[1][1], z1, w1, acc[1][1]);
        FMA2(acc[1][2], z1, w2, acc[1][2]); FMA2(acc[1][3], z1, w3, acc[1][3]);
        FMA2(acc[2][0], z2, w0, acc[2][0]); FMA2(acc[2][1], z2, w1, acc[2][1]);
        FMA2(acc[2][2], z2, w2, acc[2][2]); FMA2(acc[2][3], z2, w3, acc[2][3]);
        FMA2(acc[3][0], z3, w0, acc[3][0]); FMA2(acc[3][1], z3, w1, acc[3][1]);
        FMA2(acc[3][2], z3, w2, acc[3][2]); FMA2(acc[3][3], z3, w3, acc[3][3]);
    }

    // epilogue: unpack co pairs, store float4 across x per co plane
    {
        float* ob = out + ((size_t)b << 22) + (y << 8) + x0 + xq * 4;
        #pragma unroll
        for (int p = 0; p < 4; p++) {
            const int co = cg * 8 + 2 * p;
            float4 lo4, hi4;
            UNPACK2(lo4.x, hi4.x, acc[0][p]);
            UNPACK2(lo4.y, hi4.y, acc[1][p]);
            UNPACK2(lo4.z, hi4.z, acc[2][p]);
            UNPACK2(lo4.w, hi4.w, acc[3][p]);
            *(float4*)(ob + ((size_t)co << 16))       = lo4;
            *(float4*)(ob + ((size_t)(co + 1) << 16)) = hi4;
        }
    }
}

// ---------------------------------------------------------------------------
extern "C" void kernel_launch(void* const* d_in, const int* in_sizes, int n_in,
                              void* d_out, int out_size)
{
    const float* x       = (const float*)d_in[0];
    const float* pos_w   = (const float*)d_in[1];
    const float* pos_b   = (const float*)d_in[2];
    const float* lin_w   = (const float*)d_in[3];
    const float* att_src = (const float*)d_in[4];
    const float* att_dst = (const float*)d_in[5];
    const float* bias    = (const float*)d_in[6];
    float* out = (float*)d_out;

    gat_k1<<<512, 256>>>(x, pos_w, pos_b, lin_w, att_src, att_dst);
    gat_k2<<<1024, 256>>>(x, lin_w, pos_w, pos_b, bias, out);
}